// round 5
// baseline (speedup 1.0000x reference)
#include <cuda_runtime.h>
#include <stdint.h>

#define BATCH 128
#define N_RX 34
#define IMG_H 512
#define IMG_W 512
#define N_PIX (IMG_H * IMG_W)
#define N_PTS (BATCH * N_RX)

#define TPB 1024
#define F4_PER_THREAD 4
#define TOTAL_F4 (BATCH * 2 * N_PIX / 4)              // 16,777,216
#define GRID_BLOCKS (TOTAL_F4 / (TPB * F4_PER_THREAD)) // 4096

__device__ unsigned int g_done_ctr = 0;

// ---------------------------------------------------------------------------
// Single fused kernel: all blocks stream zeros (64B per thread, coalesced).
// The last block to finish (fence+counter protocol) performs the scatter:
// one thread per batch, 34 points in rx order => exact last-wins for free.
// Counter self-resets each launch => deterministic under graph replay.
// ---------------------------------------------------------------------------
__global__ void __launch_bounds__(TPB)
zero_scatter_kernel(const float* __restrict__ x_vecs,
                    const float* __restrict__ dw,
                    const float* __restrict__ db,
                    const float* __restrict__ cw,
                    const float* __restrict__ cb,
                    float* __restrict__ out) {
    __shared__ bool s_last;

    // ---- Zero phase: this block's contiguous 16KB slice ----
    float4* o4 = reinterpret_cast<float4*>(out);
    const size_t base = (size_t)blockIdx.x * (TPB * F4_PER_THREAD) + threadIdx.x;
    const float4 z = make_float4(0.f, 0.f, 0.f, 0.f);
    #pragma unroll
    for (int i = 0; i < F4_PER_THREAD; i++) {
        o4[base + (size_t)i * TPB] = z;
    }

    // ---- Release: make this block's stores visible, then count in ----
    __threadfence();
    __syncthreads();
    if (threadIdx.x == 0) {
        unsigned int old = atomicAdd(&g_done_ctr, 1);
        s_last = (old == GRID_BLOCKS - 1);
        if (s_last) atomicExch(&g_done_ctr, 0);   // self-reset for next replay
    }
    __syncthreads();
    if (!s_last) return;

    // ---- Scatter phase (last block only): 1 thread per batch ----
    __threadfence();   // acquire side: order after observed zero stores
    const int b = threadIdx.x;
    if (b < BATCH) {
        const float4* xv = reinterpret_cast<const float4*>(x_vecs)
                           + (size_t)b * N_RX;
        float* obase = out + (size_t)b * 2 * N_PIX;
        #pragma unroll
        for (int r = 0; r < N_RX; r++) {
            float4 v   = xv[r];
            float raw  = v.x;
            float mask = (raw != 0.0f) ? 1.0f : 0.0f;
            float p    = raw * dw[r] + mask * db[r];
            int   cat  = (int)v.w;
            p = p * cw[cat] + mask * cb[cat];
            int xx = (int)rintf(v.y);     // col 1 -> x
            int yy = (int)rintf(v.z);     // col 2 -> y
            int off = yy * IMG_W + xx;
            obase[off]         = p;       // channel 0
            obase[N_PIX + off] = raw;     // channel 1
        }
    }
}

// ---------------------------------------------------------------------------
extern "C" void kernel_launch(void* const* d_in, const int* in_sizes, int n_in,
                              void* d_out, int out_size) {
    const float* x_vecs = (const float*)d_in[0];
    const float* dw     = (const float*)d_in[1];
    const float* db     = (const float*)d_in[2];
    const float* cw     = (const float*)d_in[3];
    const float* cb     = (const float*)d_in[4];
    float* out = (float*)d_out;

    zero_scatter_kernel<<<GRID_BLOCKS, TPB>>>(x_vecs, dw, db, cw, cb, out);
}

// round 6
// speedup vs baseline: 1.0006x; 1.0006x over previous
#include <cuda_runtime.h>
#include <stdint.h>

#define BATCH 128
#define N_RX 34
#define IMG_H 512
#define IMG_W 512
#define N_PIX (IMG_H * IMG_W)

// Main streamer: 256 threads x 1 float4 = 1024 pixels (2 rows) per block.
#define TPB 256
#define PIX_PER_TILE 1024
#define TILES 256                       // per channel image (262144/1024)
// mask table: [batch][channel][tile] 64-bit occupancy (bit rr = point rr hits tile)
#define MASK_WORDS (BATCH * 2 * TILES)  // 65536

__device__ unsigned long long g_mask[MASK_WORDS];   // zero-init; invariant: all-zero at launch entry
__device__ float4 g_pt[BATCH * N_RX];               // (off_bits, p, raw, unused)

// ---------------------------------------------------------------------------
// Prologue: compute every point's value + offset, publish table + masks.
// ---------------------------------------------------------------------------
__global__ void __launch_bounds__(64)
prep_kernel(const float* __restrict__ x_vecs,
            const float* __restrict__ dw,
            const float* __restrict__ db,
            const float* __restrict__ cw,
            const float* __restrict__ cb) {
    const int b = blockIdx.x;
    const int r = threadIdx.x;
    if (r >= N_RX) return;

    const float4 v = *reinterpret_cast<const float4*>(
        x_vecs + ((size_t)b * N_RX + r) * 4);
    float raw  = v.x;
    float mask = (raw != 0.0f) ? 1.0f : 0.0f;
    float p    = raw * dw[r] + mask * db[r];
    int   cat  = (int)v.w;
    p = p * cw[cat] + mask * cb[cat];
    int xx = (int)rintf(v.y);           // col 1 -> x
    int yy = (int)rintf(v.z);           // col 2 -> y
    int off = yy * IMG_W + xx;          // pixel index within a channel image

    g_pt[b * N_RX + r] = make_float4(__int_as_float(off), p, raw, 0.f);

    int tile = off >> 10;               // / PIX_PER_TILE
    unsigned long long bit = 1ull << r;
    atomicOr(&g_mask[(b * 2 + 0) * TILES + tile], bit);
    atomicOr(&g_mask[(b * 2 + 1) * TILES + tile], bit);
}

// ---------------------------------------------------------------------------
// Main: zero-stream 256MB; blocks with occupied tiles merge point values
// into their register float4 before the single store. Fast path has NO
// barriers and NO smem — just one uniform 8B load.
// ---------------------------------------------------------------------------
__global__ void __launch_bounds__(TPB)
stream_kernel(float* __restrict__ out) {
    const int tile = blockIdx.x;        // 0..255
    const int ch   = blockIdx.y;        // 0..1
    const int b    = blockIdx.z;        // 0..127
    const int tid  = threadIdx.x;

    const int widx = (b * 2 + ch) * TILES + tile;
    const unsigned long long mask = g_mask[widx];   // uniform per block -> L2 broadcast

    float4* o4 = reinterpret_cast<float4*>(out)
               + ((size_t)(b * 2 + ch) * (N_PIX / 4)) + tile * (PIX_PER_TILE / 4) + tid;

    if (mask == 0) {                    // ~88% of blocks: pure streaming
        *o4 = make_float4(0.f, 0.f, 0.f, 0.f);
        return;
    }

    float4 acc = make_float4(0.f, 0.f, 0.f, 0.f);
    const int my_pix0 = tile * PIX_PER_TILE + tid * 4;
    unsigned long long m = mask;
    while (m) {                         // ascending rr => exact last-wins
        int rr = __ffsll((long long)m) - 1;
        m &= m - 1;
        float4 rec = g_pt[b * N_RX + rr];           // uniform -> broadcast
        int off = __float_as_int(rec.x);
        float val = ch ? rec.z : rec.y;
        int d = off - my_pix0;
        if ((unsigned)d < 4u) {
            if      (d == 0) acc.x = val;
            else if (d == 1) acc.y = val;
            else if (d == 2) acc.z = val;
            else             acc.w = val;
        }
    }
    *o4 = acc;

    // Self-clear so the table is all-zero at next launch entry (deterministic
    // under graph replay). Bar ensures every thread has read the mask first.
    __syncthreads();
    if (tid == 0) g_mask[widx] = 0;
}

// ---------------------------------------------------------------------------
extern "C" void kernel_launch(void* const* d_in, const int* in_sizes, int n_in,
                              void* d_out, int out_size) {
    const float* x_vecs = (const float*)d_in[0];
    const float* dw     = (const float*)d_in[1];
    const float* db     = (const float*)d_in[2];
    const float* cw     = (const float*)d_in[3];
    const float* cb     = (const float*)d_in[4];
    float* out = (float*)d_out;

    prep_kernel<<<BATCH, 64>>>(x_vecs, dw, db, cw, cb);

    dim3 grid(TILES, 2, BATCH);         // 65536 blocks
    stream_kernel<<<grid, TPB>>>(out);
}

// round 7
// speedup vs baseline: 1.3482x; 1.3474x over previous
#include <cuda_runtime.h>
#include <stdint.h>

#define BATCH 128
#define N_RX 34
#define IMG_H 512
#define IMG_W 512
#define N_PIX (IMG_H * IMG_W)

#define TPB 256
#define TILE_PX 1024                    // pixels per tile = TPB * 4
#define TILES_PER_GROUP 16              // 16 tiles * 4KB = 64KB per block
#define GROUPS 16                       // 16 * 16 * 1024 = 262144 = N_PIX

// ---------------------------------------------------------------------------
// Single fused kernel. Block = (group, channel, batch): 64KB contiguous span.
// Prologue computes the batch's 34 points + per-tile occupancy bitmask in
// smem; streaming loop stores zeros (fast path: LDS mask + STG only) or
// merges the few indicated points in ascending rx order (exact last-wins).
// ---------------------------------------------------------------------------
__global__ void __launch_bounds__(TPB)
vec2im_kernel(const float* __restrict__ x_vecs,
              const float* __restrict__ dw,
              const float* __restrict__ db,
              const float* __restrict__ cw,
              const float* __restrict__ cb,
              float* __restrict__ out) {
    __shared__ unsigned long long s_mask[TILES_PER_GROUP];
    __shared__ int   s_off[N_RX];
    __shared__ float s_val[N_RX];

    const int group = blockIdx.x;       // 0..15
    const int ch    = blockIdx.y;       // 0..1
    const int b     = blockIdx.z;       // 0..127
    const int tid   = threadIdx.x;

    if (tid < TILES_PER_GROUP) s_mask[tid] = 0ull;
    __syncthreads();

    // ---- Prologue: threads 0..33 each own one point of this batch ----
    if (tid < N_RX) {
        const float4 v = *reinterpret_cast<const float4*>(
            x_vecs + ((size_t)b * N_RX + tid) * 4);
        float raw  = v.x;
        float mask = (raw != 0.0f) ? 1.0f : 0.0f;
        float p    = raw * dw[tid] + mask * db[tid];
        int   cat  = (int)v.w;
        p = p * cw[cat] + mask * cb[cat];
        int xx  = (int)rintf(v.y);      // col 1 -> x
        int yy  = (int)rintf(v.z);      // col 2 -> y
        int off = yy * IMG_W + xx;
        s_off[tid] = off;
        s_val[tid] = ch ? raw : p;
        int tl = (off >> 10) - group * TILES_PER_GROUP;
        if ((unsigned)tl < (unsigned)TILES_PER_GROUP)
            atomicOr(&s_mask[tl], 1ull << tid);
    }
    __syncthreads();

    // ---- Streaming loop: 16 tiles x 4KB, one float4 per thread per tile ----
    const int px_group0 = group * (TILES_PER_GROUP * TILE_PX);
    float4* o4 = reinterpret_cast<float4*>(
                     out + (size_t)(b * 2 + ch) * N_PIX + px_group0) + tid;

    #pragma unroll
    for (int t = 0; t < TILES_PER_GROUP; t++) {
        unsigned long long m = s_mask[t];
        float4 acc = make_float4(0.f, 0.f, 0.f, 0.f);
        if (m) {
            const int my0 = px_group0 + t * TILE_PX + tid * 4;
            do {                        // ascending rr => exact last-wins
                int rr = __ffsll((long long)m) - 1;
                m &= m - 1;
                int d = s_off[rr] - my0;
                if ((unsigned)d < 4u) {
                    float val = s_val[rr];
                    if      (d == 0) acc.x = val;
                    else if (d == 1) acc.y = val;
                    else if (d == 2) acc.z = val;
                    else             acc.w = val;
                }
            } while (m);
        }
        o4[t * (TILE_PX / 4)] = acc;
    }
}

// ---------------------------------------------------------------------------
extern "C" void kernel_launch(void* const* d_in, const int* in_sizes, int n_in,
                              void* d_out, int out_size) {
    const float* x_vecs = (const float*)d_in[0];
    const float* dw     = (const float*)d_in[1];
    const float* db     = (const float*)d_in[2];
    const float* cw     = (const float*)d_in[3];
    const float* cb     = (const float*)d_in[4];
    float* out = (float*)d_out;

    dim3 grid(GROUPS, 2, BATCH);        // 4096 blocks, 64KB each
    vec2im_kernel<<<grid, TPB>>>(x_vecs, dw, db, cw, cb, out);
}